// round 3
// baseline (speedup 1.0000x reference)
#include <cuda_runtime.h>

// Problem constants (from reference): B=2, H=16, S=2048, D=64
#define BB 2
#define HH 16
#define SS 2048
#define DD 64
#define BH (BB*HH)

// ---------------------------------------------------------------------------
// Kernel 1: scores[bh, q, k] = (Q[bh,q,:] . K[bh,k,:]) / 8
// 64x64 output tile per CTA, K=64 (full depth), 256 threads, 4x4 micro-tile.
// Writes directly into the attn region of d_out.
// ---------------------------------------------------------------------------
__global__ __launch_bounds__(256) void gemm_qk_kernel(
    const float* __restrict__ q, const float* __restrict__ k,
    float* __restrict__ attn)
{
    __shared__ float Qs[64][65];
    __shared__ float Ks[64][65];

    const int bh = blockIdx.z;
    const int q0 = blockIdx.y * 64;
    const int k0 = blockIdx.x * 64;
    const float* qb = q + (size_t)bh * SS * DD;
    const float* kb = k + (size_t)bh * SS * DD;

    const int tid = threadIdx.x;

    // Load 64x64 Q tile and 64x64 K tile (row-major, D contiguous) via float4.
    // 1024 float4 per tile, 256 threads -> 4 each.
#pragma unroll
    for (int i = 0; i < 4; i++) {
        int idx = tid + i * 256;        // float4 index
        int r = idx >> 4;               // row 0..63
        int c = (idx & 15) << 2;        // col 0..60
        float4 qv = *(const float4*)(qb + (size_t)(q0 + r) * DD + c);
        Qs[r][c + 0] = qv.x; Qs[r][c + 1] = qv.y;
        Qs[r][c + 2] = qv.z; Qs[r][c + 3] = qv.w;
        float4 kv = *(const float4*)(kb + (size_t)(k0 + r) * DD + c);
        Ks[r][c + 0] = kv.x; Ks[r][c + 1] = kv.y;
        Ks[r][c + 2] = kv.z; Ks[r][c + 3] = kv.w;
    }
    __syncthreads();

    const int ty = tid >> 4;            // 0..15 (q rows)
    const int tx = tid & 15;            // 0..15 (k cols)

    float acc[4][4] = {};
#pragma unroll 16
    for (int kk = 0; kk < 64; kk++) {
        float qv[4], kv[4];
#pragma unroll
        for (int i = 0; i < 4; i++) qv[i] = Qs[ty * 4 + i][kk];
#pragma unroll
        for (int j = 0; j < 4; j++) kv[j] = Ks[tx * 4 + j][kk];
#pragma unroll
        for (int i = 0; i < 4; i++)
#pragma unroll
            for (int j = 0; j < 4; j++)
                acc[i][j] = fmaf(qv[i], kv[j], acc[i][j]);
    }

    float* ab = attn + (size_t)bh * SS * SS;
#pragma unroll
    for (int i = 0; i < 4; i++) {
        int row = q0 + ty * 4 + i;
#pragma unroll
        for (int j = 0; j < 4; j++) {
            ab[(size_t)row * SS + (k0 + tx * 4 + j)] = acc[i][j] * 0.125f;
        }
    }
}

// ---------------------------------------------------------------------------
// Kernel 2: softmax over the HEAD axis (axis=1). For each (b, q, k) position,
// normalize the 16 head values (stride S*S apart). In-place on attn region.
// ---------------------------------------------------------------------------
__global__ __launch_bounds__(256) void softmax_h_kernel(float* __restrict__ attn)
{
    size_t idx = (size_t)blockIdx.x * 256 + threadIdx.x;   // 0 .. B*S*S-1
    const size_t plane = (size_t)SS * SS;
    int b = (int)(idx / plane);
    size_t rem = idx - (size_t)b * plane;                  // q*S + k
    float* p = attn + (size_t)b * HH * plane + rem;

    float vals[HH];
    float m = -1e30f;
#pragma unroll
    for (int h = 0; h < HH; h++) {
        vals[h] = p[(size_t)h * plane];
        m = fmaxf(m, vals[h]);
    }
    float s = 0.0f;
#pragma unroll
    for (int h = 0; h < HH; h++) {
        vals[h] = __expf(vals[h] - m);
        s += vals[h];
    }
    float inv = 1.0f / s;
#pragma unroll
    for (int h = 0; h < HH; h++) {
        p[(size_t)h * plane] = vals[h] * inv;
    }
}

// ---------------------------------------------------------------------------
// Kernel 3: out[bh, q, d] = sum_k attn[bh, q, k] * v[bh, k, d]
// M=2048 (q), N=64 (d, full), K=2048. CTA: 64 q-rows x 64 d-cols, K chunks of 64.
// ---------------------------------------------------------------------------
__global__ __launch_bounds__(256) void gemm_av_kernel(
    const float* __restrict__ attn, const float* __restrict__ v,
    float* __restrict__ out)
{
    __shared__ float As[64][65];   // attn tile [q][k]
    __shared__ float Vs[64][65];   // v tile [k][d]

    const int bh = blockIdx.y;
    const int q0 = blockIdx.x * 64;
    const float* ab = attn + (size_t)bh * SS * SS;
    const float* vb = v + (size_t)bh * SS * DD;

    const int tid = threadIdx.x;
    const int ty = tid >> 4;
    const int tx = tid & 15;

    float acc[4][4] = {};

    for (int kc = 0; kc < SS; kc += 64) {
#pragma unroll
        for (int i = 0; i < 4; i++) {
            int idx = tid + i * 256;
            int r = idx >> 4;
            int c = (idx & 15) << 2;
            float4 av = *(const float4*)(ab + (size_t)(q0 + r) * SS + kc + c);
            As[r][c + 0] = av.x; As[r][c + 1] = av.y;
            As[r][c + 2] = av.z; As[r][c + 3] = av.w;
            float4 vv = *(const float4*)(vb + (size_t)(kc + r) * DD + c);
            Vs[r][c + 0] = vv.x; Vs[r][c + 1] = vv.y;
            Vs[r][c + 2] = vv.z; Vs[r][c + 3] = vv.w;
        }
        __syncthreads();

#pragma unroll 16
        for (int kk = 0; kk < 64; kk++) {
            float avr[4], vvr[4];
#pragma unroll
            for (int i = 0; i < 4; i++) avr[i] = As[ty * 4 + i][kk];
#pragma unroll
            for (int j = 0; j < 4; j++) vvr[j] = Vs[kk][tx * 4 + j];
#pragma unroll
            for (int i = 0; i < 4; i++)
#pragma unroll
                for (int j = 0; j < 4; j++)
                    acc[i][j] = fmaf(avr[i], vvr[j], acc[i][j]);
        }
        __syncthreads();
    }

    float* ob = out + (size_t)bh * SS * DD;
#pragma unroll
    for (int i = 0; i < 4; i++) {
        int row = q0 + ty * 4 + i;
#pragma unroll
        for (int j = 0; j < 4; j++) {
            ob[(size_t)row * DD + (tx * 4 + j)] = acc[i][j];
        }
    }
}

// ---------------------------------------------------------------------------
// Launch: d_out = [ out (B*H*S*D floats) | attn (B*H*S*S floats) ]
// ---------------------------------------------------------------------------
extern "C" void kernel_launch(void* const* d_in, const int* in_sizes, int n_in,
                              void* d_out, int out_size)
{
    const float* q = (const float*)d_in[0];
    const float* k = (const float*)d_in[1];
    const float* v = (const float*)d_in[2];
    // d_in[3] = feature_size (unused; scaler fixed at 8.0)

    float* out  = (float*)d_out;
    float* attn = out + (size_t)BB * HH * SS * DD;

    // 1) scores -> attn region
    {
        dim3 grid(SS / 64, SS / 64, BH);
        gemm_qk_kernel<<<grid, 256>>>(q, k, attn);
    }
    // 2) softmax over heads, in place
    {
        size_t npos = (size_t)BB * SS * SS;            // 8,388,608
        softmax_h_kernel<<<(unsigned)(npos / 256), 256>>>(attn);
    }
    // 3) out = attn @ v
    {
        dim3 grid(SS / 64, BH);
        gemm_av_kernel<<<grid, 256>>>(attn, v, out);
    }
}

// round 5
// speedup vs baseline: 2.6129x; 2.6129x over previous
#include <cuda_runtime.h>
#include <cuda_bf16.h>
#include <cstdint>

// Problem constants: B=2, H=16, S=2048, D=64
#define BB 2
#define HH 16
#define SEQ 2048
#define DIM 64
#define BH (BB*HH)

// Scratch: V transposed + bf16-split  vT[bh][d][k]  (8.4 MB each)
__device__ __nv_bfloat16 g_vT_hi[(size_t)BH * DIM * SEQ];
__device__ __nv_bfloat16 g_vT_lo[(size_t)BH * DIM * SEQ];

// ---------------------------------------------------------------------------
// Helpers
// ---------------------------------------------------------------------------
__device__ __forceinline__ uint32_t smem_u32(const void* p) {
    uint32_t a;
    asm("{ .reg .u64 t; cvta.to.shared.u64 t, %1; cvt.u32.u64 %0, t; }" : "=r"(a) : "l"(p));
    return a;
}
#define SW128(x) ((uint32_t)(x) ^ ((((uint32_t)(x)) >> 3) & 0x70))

__device__ __forceinline__ void ldmx4(uint32_t* r, uint32_t addr) {
    asm volatile("ldmatrix.sync.aligned.m8n8.x4.shared.b16 {%0,%1,%2,%3}, [%4];"
                 : "=r"(r[0]), "=r"(r[1]), "=r"(r[2]), "=r"(r[3]) : "r"(addr));
}
// D = A(16x16 bf16) * B(16x8 bf16)^T-ish (row.col) + D, fp32 acc
__device__ __forceinline__ void mma16816(float* c, const uint32_t* a, const uint32_t* b) {
    asm volatile("mma.sync.aligned.m16n8k16.row.col.f32.bf16.bf16.f32 "
                 "{%0,%1,%2,%3}, {%4,%5,%6,%7}, {%8,%9}, {%0,%1,%2,%3};"
                 : "+f"(c[0]), "+f"(c[1]), "+f"(c[2]), "+f"(c[3])
                 : "r"(a[0]), "r"(a[1]), "r"(a[2]), "r"(a[3]), "r"(b[0]), "r"(b[1]));
}

// fp32 -> bf16 hi/lo split of 8 consecutive floats
__device__ __forceinline__ void split8(const float* p, uint4& hi, uint4& lo) {
    float4 a = *(const float4*)p;
    float4 b = *(const float4*)(p + 4);
    float x[8] = {a.x, a.y, a.z, a.w, b.x, b.y, b.z, b.w};
    __nv_bfloat162* hp = (__nv_bfloat162*)&hi;
    __nv_bfloat162* lp = (__nv_bfloat162*)&lo;
#pragma unroll
    for (int i = 0; i < 4; i++) {
        __nv_bfloat16 h0 = __float2bfloat16(x[2*i]);
        __nv_bfloat16 h1 = __float2bfloat16(x[2*i+1]);
        float r0 = x[2*i]   - __bfloat162float(h0);
        float r1 = x[2*i+1] - __bfloat162float(h1);
        hp[i] = __halves2bfloat162(h0, h1);
        lp[i] = __floats2bfloat162_rn(r0, r1);
    }
}

// ---------------------------------------------------------------------------
// Kernel 0: V transpose + bf16 split  v[bh][k][d] -> vT_{hi,lo}[bh][d][k]
// ---------------------------------------------------------------------------
__global__ __launch_bounds__(256) void vsplit_kernel(const float* __restrict__ v) {
    __shared__ float s[32][33];
    int k0 = blockIdx.x * 32, d0 = blockIdx.y * 32, bh = blockIdx.z;
    const float* vb = v + (size_t)bh * SEQ * DIM;
    int t = threadIdx.x;
#pragma unroll
    for (int i = 0; i < 4; i++) {
        int e = t + i * 256;
        int kk = e >> 5, dd = e & 31;
        s[kk][dd] = vb[(size_t)(k0 + kk) * DIM + d0 + dd];
    }
    __syncthreads();
#pragma unroll
    for (int i = 0; i < 4; i++) {
        int e = t + i * 256;
        int dd = e >> 5, kk = e & 31;
        float x = s[kk][dd];
        __nv_bfloat16 h = __float2bfloat16(x);
        __nv_bfloat16 l = __float2bfloat16(x - __bfloat162float(h));
        size_t o = ((size_t)bh * DIM + d0 + dd) * SEQ + k0 + kk;
        g_vT_hi[o] = h;
        g_vT_lo[o] = l;
    }
}

// ---------------------------------------------------------------------------
// Kernel 1: scores = (Q . K^T)/8 via mma.sync bf16 hi/lo split.
// CTA: 128q x 128k, 256 threads = 8 warps (2 rows x 4 cols of 64x32 tiles).
// smem: QHI | QLO | KHI | KLO, each 128x64 bf16 SW128 = 16KB -> 64KB total.
// ---------------------------------------------------------------------------
#define QK_QHI 0u
#define QK_QLO 16384u
#define QK_KHI 32768u
#define QK_KLO 49152u
#define QK_SMEM 65536

__global__ __launch_bounds__(256) void qk_mma_kernel(
    const float* __restrict__ q, const float* __restrict__ k,
    float* __restrict__ attn)
{
    extern __shared__ char smem[];
    uint32_t sbase = smem_u32(smem);
    const int tid = threadIdx.x;
    const int wid = tid >> 5;
    const int lane = tid & 31;
    const int wr = wid >> 2;        // 0..1  q-row of warp (64 rows)
    const int wc = wid & 3;         // 0..3  k-col of warp (32 cols)

    const int bh = blockIdx.z;
    const int q0 = blockIdx.y * 128;
    const int k0 = blockIdx.x * 128;
    const float* qb = q + ((size_t)bh * SEQ + q0) * DIM;
    const float* kb = k + ((size_t)bh * SEQ + k0) * DIM;

    // Stage Q and K (128x64 fp32 each) as split bf16, SW128 swizzled 128B rows
    for (int t = tid; t < 1024; t += 256) {
        int row = t >> 3, c0 = (t & 7) << 3;
        uint32_t off = SW128(row * 128 + c0 * 2);
        uint4 hi, lo;
        split8(qb + (size_t)row * DIM + c0, hi, lo);
        *(uint4*)(smem + QK_QHI + off) = hi;
        *(uint4*)(smem + QK_QLO + off) = lo;
        split8(kb + (size_t)row * DIM + c0, hi, lo);
        *(uint4*)(smem + QK_KHI + off) = hi;
        *(uint4*)(smem + QK_KLO + off) = lo;
    }
    __syncthreads();

    float acc[4][4][4];             // [m-block][n-block][frag]
#pragma unroll
    for (int m = 0; m < 4; m++)
#pragma unroll
        for (int n = 0; n < 4; n++)
#pragma unroll
            for (int i = 0; i < 4; i++) acc[m][n][i] = 0.0f;

    // A-frag address: row = wr*64 + mf*16 + (lane&15), colByte = kc*2 + (lane>>4)*16
    // B-frag pair p: row = wc*32 + p*16 + ((lane>>4)<<3) + (lane&7),
    //                colByte = kc*2 + ((lane>>3)&1)*16
    const int a_row = wr * 64 + (lane & 15);
    const int a_cb  = (lane >> 4) << 4;
    const int b_row = wc * 32 + ((lane >> 4) << 3) + (lane & 7);
    const int b_cb  = ((lane >> 3) & 1) << 4;

#pragma unroll
    for (int kc = 0; kc < 4; kc++) {                  // K in 4 chunks of 16
        const int kb16 = kc * 32;                     // byte offset of k-chunk
        uint32_t Ahi[4][4], Alo[4][4];
#pragma unroll
        for (int m = 0; m < 4; m++) {
            uint32_t off = SW128((a_row + m * 16) * 128 + kb16 + a_cb);
            ldmx4(Ahi[m], sbase + QK_QHI + off);
            ldmx4(Alo[m], sbase + QK_QLO + off);
        }
        uint32_t Bhi[2][4], Blo[2][4];                // pairs: n-blocks {0,1},{2,3}
#pragma unroll
        for (int p = 0; p < 2; p++) {
            uint32_t off = SW128((b_row + p * 16) * 128 + kb16 + b_cb);
            ldmx4(Bhi[p], sbase + QK_KHI + off);
            ldmx4(Blo[p], sbase + QK_KLO + off);
        }
#pragma unroll
        for (int m = 0; m < 4; m++)
#pragma unroll
            for (int n = 0; n < 4; n++) {
                const uint32_t* bh2 = &Bhi[n >> 1][(n & 1) * 2];
                const uint32_t* bl2 = &Blo[n >> 1][(n & 1) * 2];
                mma16816(acc[m][n], Ahi[m], bh2);
                mma16816(acc[m][n], Ahi[m], bl2);
                mma16816(acc[m][n], Alo[m], bh2);
            }
    }

    // Store scores * 0.125 directly (each quad covers a 32B sector)
    float* ab = attn + ((size_t)bh * SEQ + q0) * SEQ + k0;
    const int er = (lane >> 2);
    const int ec = (lane & 3) * 2;
#pragma unroll
    for (int m = 0; m < 4; m++) {
        int row = wr * 64 + m * 16 + er;
#pragma unroll
        for (int n = 0; n < 4; n++) {
            int col = wc * 32 + n * 8 + ec;
            float2 v0 = { acc[m][n][0] * 0.125f, acc[m][n][1] * 0.125f };
            float2 v1 = { acc[m][n][2] * 0.125f, acc[m][n][3] * 0.125f };
            *(float2*)(ab + (size_t)row * SEQ + col) = v0;
            *(float2*)(ab + (size_t)(row + 8) * SEQ + col) = v1;
        }
    }
}

// ---------------------------------------------------------------------------
// Kernel 2: softmax over HEAD axis, in-place on attn
// ---------------------------------------------------------------------------
__global__ __launch_bounds__(256) void softmax_h_kernel(float* __restrict__ attn)
{
    size_t idx = (size_t)blockIdx.x * 256 + threadIdx.x;
    const size_t plane = (size_t)SEQ * SEQ;
    int b = (int)(idx / plane);
    size_t rem = idx - (size_t)b * plane;
    float* p = attn + (size_t)b * HH * plane + rem;

    float vals[HH];
    float m = -1e30f;
#pragma unroll
    for (int h = 0; h < HH; h++) {
        vals[h] = p[(size_t)h * plane];
        m = fmaxf(m, vals[h]);
    }
    float s = 0.0f;
#pragma unroll
    for (int h = 0; h < HH; h++) {
        vals[h] = __expf(vals[h] - m);
        s += vals[h];
    }
    float inv = 1.0f / s;
#pragma unroll
    for (int h = 0; h < HH; h++)
        p[(size_t)h * plane] = vals[h] * inv;
}

// ---------------------------------------------------------------------------
// Kernel 3: out = attn @ V via mma.sync, hi/lo split.
// CTA: 128q x 64d, 256 threads = 8 warps (4 q-rows x 2 d-cols of 32x32 tiles).
// K=2048 in 32 chunks of 64, double-buffered smem with register prefetch.
// Buffer: AHI 16K | ALO 16K | VHI 8K | VLO 8K = 48K; x2 = 96K.
// ---------------------------------------------------------------------------
#define AVB 49152u
#define AV_AHI 0u
#define AV_ALO 16384u
#define AV_VHI 32768u
#define AV_VLO 40960u
#define AV_SMEM 98304

__global__ __launch_bounds__(256) void av_mma_kernel(
    const float* __restrict__ attn, float* __restrict__ out)
{
    extern __shared__ char smem[];
    uint32_t sbase = smem_u32(smem);
    const int tid = threadIdx.x;
    const int wid = tid >> 5;
    const int lane = tid & 31;
    const int wr = wid >> 1;        // 0..3 q-row (32 rows)
    const int wc = wid & 1;         // 0..1 d-col (32 cols)

    const int bh = blockIdx.y;
    const int q0 = blockIdx.x * 128;
    const float* ab = attn + ((size_t)bh * SEQ + q0) * SEQ;
    const __nv_bfloat16* vh = g_vT_hi + (size_t)bh * DIM * SEQ;
    const __nv_bfloat16* vl = g_vT_lo + (size_t)bh * DIM * SEQ;

    // staging indices (per thread): A: 4 groups of 8 floats; V: 2 uint4 per arr
    const int sa_row = tid >> 3;               // 0..31 (x4 passes of 32 rows)
    const int sa_c0  = (tid & 7) << 3;         // 0,8,..,56
    const int sv_row = tid >> 2;               // 0..63
    const int sv_c0  = (tid & 3) << 4;         // byte col 0..48 (x2 passes)

    float acc[2][4][4];
#pragma unroll
    for (int m = 0; m < 2; m++)
#pragma unroll
        for (int n = 0; n < 4; n++)
#pragma unroll
            for (int i = 0; i < 4; i++) acc[m][n][i] = 0.0f;

    const int a_row = wr * 32 + (lane & 15);
    const int a_cb  = (lane >> 4) << 4;
    const int b_row = wc * 32 + ((lane >> 4) << 3) + (lane & 7);
    const int b_cb  = ((lane >> 3) & 1) << 4;

    uint4 pAhi[4], pAlo[4], pVhi[2], pVlo[2];

    // ---- prologue: load + store chunk 0
#pragma unroll
    for (int i = 0; i < 4; i++)
        split8(ab + (size_t)(sa_row + i * 32) * SEQ + sa_c0, pAhi[i], pAlo[i]);
#pragma unroll
    for (int i = 0; i < 2; i++) {
        size_t gi = (size_t)(sv_row) * SEQ + (sv_c0 >> 1) + i * 32;
        pVhi[i] = *(const uint4*)(vh + gi);
        pVlo[i] = *(const uint4*)(vl + gi);
    }
#pragma unroll
    for (int i = 0; i < 4; i++) {
        uint32_t off = SW128((sa_row + i * 32) * 128 + sa_c0 * 2);
        *(uint4*)(smem + AV_AHI + off) = pAhi[i];
        *(uint4*)(smem + AV_ALO + off) = pAlo[i];
    }
#pragma unroll
    for (int i = 0; i < 2; i++) {
        uint32_t off = SW128(sv_row * 128 + sv_c0 + i * 64);
        *(uint4*)(smem + AV_VHI + off) = pVhi[i];
        *(uint4*)(smem + AV_VLO + off) = pVlo[i];
    }
    __syncthreads();

    for (int it = 0; it < 32; it++) {
        const uint32_t bo = (it & 1) * AVB;
        // prefetch next chunk into registers
        if (it < 31) {
            int kc0 = (it + 1) * 64;
#pragma unroll
            for (int i = 0; i < 4; i++)
                split8(ab + (size_t)(sa_row + i * 32) * SEQ + kc0 + sa_c0,
                       pAhi[i], pAlo[i]);
#pragma unroll
            for (int i = 0; i < 2; i++) {
                size_t gi = (size_t)(sv_row) * SEQ + kc0 + (sv_c0 >> 1) + i * 32;
                pVhi[i] = *(const uint4*)(vh + gi);
                pVlo[i] = *(const uint4*)(vl + gi);
            }
        }
        // compute on current buffer
#pragma unroll
        for (int kc = 0; kc < 4; kc++) {
            const int kb16 = kc * 32;
            uint32_t Ahi[2][4], Alo[2][4];
#pragma unroll
            for (int m = 0; m < 2; m++) {
                uint32_t off = SW128((a_row + m * 16) * 128 + kb16 + a_cb);
                ldmx4(Ahi[m], sbase + bo + AV_AHI + off);
                ldmx4(Alo[m], sbase + bo + AV_ALO + off);
            }
            uint32_t Bhi[2][4], Blo[2][4];
#pragma unroll
            for (int p = 0; p < 2; p++) {
                uint32_t off = SW128((b_row + p * 16) * 128 + kb16 + b_cb);
                ldmx4(Bhi[p], sbase + bo + AV_VHI + off);
                ldmx4(Blo[p], sbase + bo + AV_VLO + off);
            }
#pragma unroll
            for (int m = 0; m < 2; m++)
#pragma unroll
                for (int n = 0; n < 4; n++) {
                    const uint32_t* bh2 = &Bhi[n >> 1][(n & 1) * 2];
                    const uint32_t* bl2 = &Blo[n >> 1][(n & 1) * 2];
                    mma16816(acc[m][n], Ahi[m], bh2);
                    mma16816(acc[m][n], Ahi[m], bl2);
                    mma16816(acc[m][n], Alo[m], bh2);
                }
        }
        // store prefetched regs into the other buffer
        if (it < 31) {
            const uint32_t bn = ((it + 1) & 1) * AVB;
#pragma unroll
            for (int i = 0; i < 4; i++) {
                uint32_t off = SW128((sa_row + i * 32) * 128 + sa_c0 * 2);
                *(uint4*)(smem + bn + AV_AHI + off) = pAhi[i];
                *(uint4*)(smem + bn + AV_ALO + off) = pAlo[i];
            }
#pragma unroll
            for (int i = 0; i < 2; i++) {
                uint32_t off = SW128(sv_row * 128 + sv_c0 + i * 64);
                *(uint4*)(smem + bn + AV_VHI + off) = pVhi[i];
                *(uint4*)(smem + bn + AV_VLO + off) = pVlo[i];
            }
            __syncthreads();
        }
    }

    // epilogue: direct stores
    float* ob = out + ((size_t)bh * SEQ + q0) * DIM;
    const int er = (lane >> 2);
    const int ec = (lane & 3) * 2;
#pragma unroll
    for (int m = 0; m < 2; m++) {
        int row = wr * 32 + m * 16 + er;
#pragma unroll
        for (int n = 0; n < 4; n++) {
            int col = wc * 32 + n * 8 + ec;
            float2 v0 = { acc[m][n][0], acc[m][n][1] };
            float2 v1 = { acc[m][n][2], acc[m][n][3] };
            *(float2*)(ob + (size_t)row * DIM + col) = v0;
            *(float2*)(ob + (size_t)(row + 8) * DIM + col) = v1;
        }
    }
}

// ---------------------------------------------------------------------------
// Launch: d_out = [ out (B*H*S*D) | attn (B*H*S*S) ]
// ---------------------------------------------------------------------------
extern "C" void kernel_launch(void* const* d_in, const int* in_sizes, int n_in,
                              void* d_out, int out_size)
{
    const float* q = (const float*)d_in[0];
    const float* k = (const float*)d_in[1];
    const float* v = (const float*)d_in[2];

    float* out  = (float*)d_out;
    float* attn = out + (size_t)BB * HH * SEQ * DIM;

    cudaFuncSetAttribute(qk_mma_kernel, cudaFuncAttributeMaxDynamicSharedMemorySize, QK_SMEM);
    cudaFuncSetAttribute(av_mma_kernel, cudaFuncAttributeMaxDynamicSharedMemorySize, AV_SMEM);

    // 0) V transpose + split
    {
        dim3 grid(SEQ / 32, DIM / 32, BH);
        vsplit_kernel<<<grid, 256>>>(v);
    }
    // 1) raw scores -> attn region (tensor cores via mma.sync)
    {
        dim3 grid(SEQ / 128, SEQ / 128, BH);
        qk_mma_kernel<<<grid, 256, QK_SMEM>>>(q, k, attn);
    }
    // 2) softmax over heads, in place
    {
        size_t npos = (size_t)BB * SEQ * SEQ;
        softmax_h_kernel<<<(unsigned)(npos / 256), 256>>>(attn);
    }
    // 3) out = attn @ V (tensor cores via mma.sync)
    {
        dim3 grid(SEQ / 128, BH);
        av_mma_kernel<<<grid, 256, AV_SMEM>>>(attn, out);
    }
}